// round 5
// baseline (speedup 1.0000x reference)
#include <cuda_runtime.h>

#define DIM   2048
#define NVEC  32768          // B*T*N = 2*4096*4
#define VPB   16             // vectors per block
#define NBLK  (NVEC / VPB)   // 2048
#define EPS   1e-6f
#define PSTRIDE 72           // padded partial row (words): sel*8+g hits all banks

typedef unsigned long long u64;

__device__ __forceinline__ void fma2(u64& d, u64 a, u64 b) {
    asm("fma.rn.f32x2 %0, %1, %2, %0;" : "+l"(d) : "l"(a), "l"(b));
}
__device__ __forceinline__ u64 pack2(float x, float y) {
    u64 r;
    asm("mov.b64 %0, {%1, %2};" : "=l"(r) : "f"(x), "f"(y));
    return r;
}
__device__ __forceinline__ float hsum2(u64 a) {
    float lo, hi;
    asm("mov.b64 {%0, %1}, %2;" : "=f"(lo), "=f"(hi) : "l"(a));
    return lo + hi;
}
__device__ __forceinline__ float4 mul4(float4 a, float4 b) {
    return make_float4(a.x * b.x, a.y * b.y, a.z * b.z, a.w * b.w);
}

__global__ void __launch_bounds__(256, 3)
hcmaps_kernel(const float* __restrict__ x,
              const float* __restrict__ rmsw,
              const float* __restrict__ alpha_pre,
              const float* __restrict__ alpha_post,
              const float* __restrict__ alpha_res,
              const float* __restrict__ th_pre,
              const float* __restrict__ th_post,
              const float* __restrict__ th_res,
              const float* __restrict__ b_pre,
              const float* __restrict__ b_post,
              const float* __restrict__ b_res,
              float* __restrict__ out)
{
    const int t    = threadIdx.x;
    const int lane = t & 31;
    const int wrp  = t >> 5;
    const int cA   = 4 * t;          // columns cA..cA+3
    const int cB   = 1024 + 4 * t;   // columns cB..cB+3

    // Fold rms_weight into thetas once per block; pack as f32x2 pairs.
    const float4 wA = *(const float4*)(rmsw + cA);
    const float4 wB = *(const float4*)(rmsw + cB);

    float4 f;
    f = mul4(*(const float4*)(th_pre  + cA), wA);
    const u64 pA0 = pack2(f.x, f.y), pA1 = pack2(f.z, f.w);
    f = mul4(*(const float4*)(th_pre  + cB), wB);
    const u64 pB0 = pack2(f.x, f.y), pB1 = pack2(f.z, f.w);
    f = mul4(*(const float4*)(th_post + cA), wA);
    const u64 qA0 = pack2(f.x, f.y), qA1 = pack2(f.z, f.w);
    f = mul4(*(const float4*)(th_post + cB), wB);
    const u64 qB0 = pack2(f.x, f.y), qB1 = pack2(f.z, f.w);
    f = mul4(*(const float4*)(th_res + 0 * DIM + cA), wA);
    const u64 r0A0 = pack2(f.x, f.y), r0A1 = pack2(f.z, f.w);
    f = mul4(*(const float4*)(th_res + 0 * DIM + cB), wB);
    const u64 r0B0 = pack2(f.x, f.y), r0B1 = pack2(f.z, f.w);
    f = mul4(*(const float4*)(th_res + 1 * DIM + cA), wA);
    const u64 r1A0 = pack2(f.x, f.y), r1A1 = pack2(f.z, f.w);
    f = mul4(*(const float4*)(th_res + 1 * DIM + cB), wB);
    const u64 r1B0 = pack2(f.x, f.y), r1B1 = pack2(f.z, f.w);
    f = mul4(*(const float4*)(th_res + 2 * DIM + cA), wA);
    const u64 r2A0 = pack2(f.x, f.y), r2A1 = pack2(f.z, f.w);
    f = mul4(*(const float4*)(th_res + 2 * DIM + cB), wB);
    const u64 r2B0 = pack2(f.x, f.y), r2B1 = pack2(f.z, f.w);
    f = mul4(*(const float4*)(th_res + 3 * DIM + cA), wA);
    const u64 r3A0 = pack2(f.x, f.y), r3A1 = pack2(f.z, f.w);
    f = mul4(*(const float4*)(th_res + 3 * DIM + cB), wB);
    const u64 r3B0 = pack2(f.x, f.y), r3B1 = pack2(f.z, f.w);

    // 64-wide partials per (vector, sum); reduced once in the epilogue.
    __shared__ float part[VPB][7][PSTRIDE];
    __shared__ float tot[VPB][7];

    const int v0 = blockIdx.x * VPB;
    const ulonglong2* xbase = (const ulonglong2*)(x + (size_t)v0 * DIM);

    // Prime the register double-buffer (each ulonglong2 = one float4).
    ulonglong2 xA = xbase[t];
    ulonglong2 xB = xbase[256 + t];

    for (int vi = 0; vi < VPB; ++vi) {
        // Prefetch the next vector before any math on the current one.
        ulonglong2 nA, nB;
        if (vi + 1 < VPB) {
            const ulonglong2* xn = xbase + (size_t)(vi + 1) * (DIM / 4);
            nA = xn[t];
            nB = xn[256 + t];
        }

        u64 a0 = 0, a1 = 0, a2 = 0, a3 = 0, a4 = 0, a5 = 0, a6 = 0;

        fma2(a0, xA.x, xA.x); fma2(a0, xA.y, xA.y);
        fma2(a0, xB.x, xB.x); fma2(a0, xB.y, xB.y);      // sum of squares

        fma2(a1, pA0, xA.x);  fma2(a1, pA1, xA.y);
        fma2(a1, pB0, xB.x);  fma2(a1, pB1, xB.y);       // theta_pre

        fma2(a2, qA0, xA.x);  fma2(a2, qA1, xA.y);
        fma2(a2, qB0, xB.x);  fma2(a2, qB1, xB.y);       // theta_post

        fma2(a3, r0A0, xA.x); fma2(a3, r0A1, xA.y);
        fma2(a3, r0B0, xB.x); fma2(a3, r0B1, xB.y);      // theta_res rows

        fma2(a4, r1A0, xA.x); fma2(a4, r1A1, xA.y);
        fma2(a4, r1B0, xB.x); fma2(a4, r1B1, xB.y);

        fma2(a5, r2A0, xA.x); fma2(a5, r2A1, xA.y);
        fma2(a5, r2B0, xB.x); fma2(a5, r2B1, xB.y);

        fma2(a6, r3A0, xA.x); fma2(a6, r3A1, xA.y);
        fma2(a6, r3B0, xB.x); fma2(a6, r3B1, xB.y);

        float s0 = hsum2(a0), s1 = hsum2(a1), s2 = hsum2(a2), s3 = hsum2(a3);
        float s4 = hsum2(a4), s5 = hsum2(a5), s6 = hsum2(a6);

        // Depth-2 shuffle: each 4-lane group ends holding its group totals.
        s0 += __shfl_xor_sync(0xffffffffu, s0, 1);
        s1 += __shfl_xor_sync(0xffffffffu, s1, 1);
        s2 += __shfl_xor_sync(0xffffffffu, s2, 1);
        s3 += __shfl_xor_sync(0xffffffffu, s3, 1);
        s4 += __shfl_xor_sync(0xffffffffu, s4, 1);
        s5 += __shfl_xor_sync(0xffffffffu, s5, 1);
        s6 += __shfl_xor_sync(0xffffffffu, s6, 1);
        s0 += __shfl_xor_sync(0xffffffffu, s0, 2);
        s1 += __shfl_xor_sync(0xffffffffu, s1, 2);
        s2 += __shfl_xor_sync(0xffffffffu, s2, 2);
        s3 += __shfl_xor_sync(0xffffffffu, s3, 2);
        s4 += __shfl_xor_sync(0xffffffffu, s4, 2);
        s5 += __shfl_xor_sync(0xffffffffu, s5, 2);
        s6 += __shfl_xor_sync(0xffffffffu, s6, 2);

        // 4-way select: lane with sel=k holds sum k's group total.
        const int sel = lane & 3;
        const int g   = wrp * 8 + (lane >> 2);           // 0..63
        const float vA4 = (sel == 0) ? s0 : (sel == 1) ? s1 : (sel == 2) ? s2 : s3;
        const float vB4 = (sel == 0) ? s4 : (sel == 1) ? s5 : s6;

        part[vi][sel][g] = vA4;                           // sums 0..3, conflict-free
        if (sel < 3) part[vi][4 + sel][g] = vB4;          // sums 4..6

        xA = nA;
        xB = nB;
    }

    __syncthreads();

    // Phase A: reduce the 64 partials for each (vector, sum).
    if (t < 112) {
        const int v = t / 7;
        const int k = t % 7;
        const float* p = &part[v][k][0];
        float a = 0.0f;
#pragma unroll
        for (int j = 0; j < 64; ++j) a += p[(j + t) & 63];   // rotation dodges conflicts
        tot[v][k] = a;
    }
    __syncthreads();

    // Phase B: 6 outputs per vector, one thread each.
    if (t < 128) {
        const int v = t >> 3;     // local vector 0..15
        const int j = t & 7;      // output slot (6 used)
        if (j < 6) {
            const int gv = v0 + v;
            const int n  = gv & 3;
            const int bt = gv >> 2;
            const float scale = rsqrtf(tot[v][0] * (1.0f / DIM) + EPS);
            if (j == 0) {
                out[gv] = fmaf(alpha_pre[0], tanhf(tot[v][1] * scale), b_pre[n]);
            } else if (j == 1) {
                out[NVEC + gv] = fmaf(alpha_post[0], tanhf(tot[v][2] * scale), b_post[n]);
            } else {
                const int i = j - 2;   // residual row 0..3
                out[2 * NVEC + bt * 16 + i * 4 + n] =
                    fmaf(alpha_res[0], tanhf(tot[v][3 + i] * scale), b_res[4 * i + n]);
            }
        }
    }
}

extern "C" void kernel_launch(void* const* d_in, const int* in_sizes, int n_in,
                              void* d_out, int out_size)
{
    const float* x      = (const float*)d_in[0];   // [2,4096,4,2048]
    const float* rmsw   = (const float*)d_in[1];   // [2048]
    const float* apre   = (const float*)d_in[2];   // scalar
    const float* apost  = (const float*)d_in[3];   // scalar
    const float* ares   = (const float*)d_in[4];   // scalar
    const float* tpre   = (const float*)d_in[5];   // [2048]
    const float* tpost  = (const float*)d_in[6];   // [2048]
    const float* tres   = (const float*)d_in[7];   // [4,2048]
    const float* bpre   = (const float*)d_in[8];   // [4]
    const float* bpost  = (const float*)d_in[9];   // [4]
    const float* bres   = (const float*)d_in[10];  // [4,4]
    float* out = (float*)d_out;

    hcmaps_kernel<<<NBLK, 256>>>(x, rmsw, apre, apost, ares,
                                 tpre, tpost, tres, bpre, bpost, bres, out);
}

// round 7
// speedup vs baseline: 1.3331x; 1.3331x over previous
#include <cuda_runtime.h>
#include <cstdint>

#define DIM     2048
#define NVEC    32768          // B*T*N = 2*4096*4
#define VPB     16             // vectors per block
#define NBLK    (NVEC / VPB)   // 2048
#define EPS     1e-6f
#define PSTRIDE 72             // padded partial row (words)
#define STAGES  4
#define LOOK    3              // prefetch lookahead (= STAGES-1)

#define XS_FLOATS   (STAGES * DIM)                 // 8192 floats = 32 KB
#define PART_OFF    XS_FLOATS                      // partials follow ring
#define DSMEM_BYTES ((XS_FLOATS + VPB * 7 * PSTRIDE) * 4)   // 65024 B

typedef unsigned long long u64;
typedef unsigned int       u32;

__device__ __forceinline__ void fma2(u64& d, u64 a, u64 b) {
    asm("fma.rn.f32x2 %0, %1, %2, %0;" : "+l"(d) : "l"(a), "l"(b));
}
__device__ __forceinline__ u64 pack2(float x, float y) {
    u64 r;
    asm("mov.b64 %0, {%1, %2};" : "=l"(r) : "f"(x), "f"(y));
    return r;
}
__device__ __forceinline__ float hsum2(u64 a) {
    float lo, hi;
    asm("mov.b64 {%0, %1}, %2;" : "=f"(lo), "=f"(hi) : "l"(a));
    return lo + hi;
}
__device__ __forceinline__ float4 mul4(float4 a, float4 b) {
    return make_float4(a.x * b.x, a.y * b.y, a.z * b.z, a.w * b.w);
}
__device__ __forceinline__ void cp16(u32 smem_dst, const void* gsrc) {
    asm volatile("cp.async.cg.shared.global [%0], [%1], 16;"
                 :: "r"(smem_dst), "l"(gsrc));
}
#define CP_COMMIT()  asm volatile("cp.async.commit_group;" ::: "memory")
#define CP_WAIT(N)   asm volatile("cp.async.wait_group %0;" :: "n"(N) : "memory")

__global__ void __launch_bounds__(256, 3)
hcmaps_kernel(const float* __restrict__ x,
              const float* __restrict__ rmsw,
              const float* __restrict__ alpha_pre,
              const float* __restrict__ alpha_post,
              const float* __restrict__ alpha_res,
              const float* __restrict__ th_pre,
              const float* __restrict__ th_post,
              const float* __restrict__ th_res,
              const float* __restrict__ b_pre,
              const float* __restrict__ b_post,
              const float* __restrict__ b_res,
              float* __restrict__ out)
{
    extern __shared__ float dsm[];
    float* xs = dsm;                                        // [STAGES][DIM]
    float (*part)[7][PSTRIDE] = (float (*)[7][PSTRIDE])(dsm + PART_OFF);
    __shared__ float tot[VPB][7];

    const int t    = threadIdx.x;
    const int lane = t & 31;
    const int wrp  = t >> 5;
    const int cA   = 4 * t;
    const int cB   = 1024 + 4 * t;

    const int v0 = blockIdx.x * VPB;
    const float* xg = x + (size_t)v0 * DIM;

    // smem u32 addresses of this thread's two 16B slots in each stage
    const u32 xs_u32 = (u32)__cvta_generic_to_shared(xs);
    const u32 offA = (u32)cA * 4u;     // byte offset of slot A within a stage
    const u32 offB = (u32)cB * 4u;

    // ---- Prologue: start LOOK stages of prefetch immediately. ----
#pragma unroll
    for (int s = 0; s < LOOK; ++s) {
        const float* src = xg + (size_t)s * DIM;
        const u32 dst = xs_u32 + (u32)s * (DIM * 4u);
        cp16(dst + offA, src + cA);
        cp16(dst + offB, src + cB);
        CP_COMMIT();
    }

    // ---- Fold rms_weight into thetas (overlaps with in-flight cp.async). ----
    const float4 wA = *(const float4*)(rmsw + cA);
    const float4 wB = *(const float4*)(rmsw + cB);

    float4 f;
    f = mul4(*(const float4*)(th_pre  + cA), wA);
    const u64 pA0 = pack2(f.x, f.y), pA1 = pack2(f.z, f.w);
    f = mul4(*(const float4*)(th_pre  + cB), wB);
    const u64 pB0 = pack2(f.x, f.y), pB1 = pack2(f.z, f.w);
    f = mul4(*(const float4*)(th_post + cA), wA);
    const u64 qA0 = pack2(f.x, f.y), qA1 = pack2(f.z, f.w);
    f = mul4(*(const float4*)(th_post + cB), wB);
    const u64 qB0 = pack2(f.x, f.y), qB1 = pack2(f.z, f.w);
    f = mul4(*(const float4*)(th_res + 0 * DIM + cA), wA);
    const u64 r0A0 = pack2(f.x, f.y), r0A1 = pack2(f.z, f.w);
    f = mul4(*(const float4*)(th_res + 0 * DIM + cB), wB);
    const u64 r0B0 = pack2(f.x, f.y), r0B1 = pack2(f.z, f.w);
    f = mul4(*(const float4*)(th_res + 1 * DIM + cA), wA);
    const u64 r1A0 = pack2(f.x, f.y), r1A1 = pack2(f.z, f.w);
    f = mul4(*(const float4*)(th_res + 1 * DIM + cB), wB);
    const u64 r1B0 = pack2(f.x, f.y), r1B1 = pack2(f.z, f.w);
    f = mul4(*(const float4*)(th_res + 2 * DIM + cA), wA);
    const u64 r2A0 = pack2(f.x, f.y), r2A1 = pack2(f.z, f.w);
    f = mul4(*(const float4*)(th_res + 2 * DIM + cB), wB);
    const u64 r2B0 = pack2(f.x, f.y), r2B1 = pack2(f.z, f.w);
    f = mul4(*(const float4*)(th_res + 3 * DIM + cA), wA);
    const u64 r3A0 = pack2(f.x, f.y), r3A1 = pack2(f.z, f.w);
    f = mul4(*(const float4*)(th_res + 3 * DIM + cB), wB);
    const u64 r3B0 = pack2(f.x, f.y), r3B1 = pack2(f.z, f.w);

    // ---- Mainloop: barrier-free (each thread reads only what it copied). ----
    for (int vi = 0; vi < VPB; ++vi) {
        // Issue the next prefetch first (keeps LOOK groups in flight).
        if (vi + LOOK < VPB) {
            const float* src = xg + (size_t)(vi + LOOK) * DIM;
            const u32 dst = xs_u32 + (u32)((vi + LOOK) & (STAGES - 1)) * (DIM * 4u);
            cp16(dst + offA, src + cA);
            cp16(dst + offB, src + cB);
        }
        CP_COMMIT();                 // commit every iteration to keep accounting
        CP_WAIT(LOOK);               // group for vector vi is now complete

        const float* stage = xs + (vi & (STAGES - 1)) * DIM;
        const ulonglong2 xA = *(const ulonglong2*)(stage + cA);
        const ulonglong2 xB = *(const ulonglong2*)(stage + cB);

        u64 a0 = 0, a1 = 0, a2 = 0, a3 = 0, a4 = 0, a5 = 0, a6 = 0;

        fma2(a0, xA.x, xA.x); fma2(a0, xA.y, xA.y);
        fma2(a0, xB.x, xB.x); fma2(a0, xB.y, xB.y);      // sum of squares

        fma2(a1, pA0, xA.x);  fma2(a1, pA1, xA.y);
        fma2(a1, pB0, xB.x);  fma2(a1, pB1, xB.y);       // theta_pre

        fma2(a2, qA0, xA.x);  fma2(a2, qA1, xA.y);
        fma2(a2, qB0, xB.x);  fma2(a2, qB1, xB.y);       // theta_post

        fma2(a3, r0A0, xA.x); fma2(a3, r0A1, xA.y);
        fma2(a3, r0B0, xB.x); fma2(a3, r0B1, xB.y);      // theta_res rows

        fma2(a4, r1A0, xA.x); fma2(a4, r1A1, xA.y);
        fma2(a4, r1B0, xB.x); fma2(a4, r1B1, xB.y);

        fma2(a5, r2A0, xA.x); fma2(a5, r2A1, xA.y);
        fma2(a5, r2B0, xB.x); fma2(a5, r2B1, xB.y);

        fma2(a6, r3A0, xA.x); fma2(a6, r3A1, xA.y);
        fma2(a6, r3B0, xB.x); fma2(a6, r3B1, xB.y);

        float s0 = hsum2(a0), s1 = hsum2(a1), s2 = hsum2(a2), s3 = hsum2(a3);
        float s4 = hsum2(a4), s5 = hsum2(a5), s6 = hsum2(a6);

        // Depth-2 shuffle: each 4-lane group ends holding its group totals.
        s0 += __shfl_xor_sync(0xffffffffu, s0, 1);
        s1 += __shfl_xor_sync(0xffffffffu, s1, 1);
        s2 += __shfl_xor_sync(0xffffffffu, s2, 1);
        s3 += __shfl_xor_sync(0xffffffffu, s3, 1);
        s4 += __shfl_xor_sync(0xffffffffu, s4, 1);
        s5 += __shfl_xor_sync(0xffffffffu, s5, 1);
        s6 += __shfl_xor_sync(0xffffffffu, s6, 1);
        s0 += __shfl_xor_sync(0xffffffffu, s0, 2);
        s1 += __shfl_xor_sync(0xffffffffu, s1, 2);
        s2 += __shfl_xor_sync(0xffffffffu, s2, 2);
        s3 += __shfl_xor_sync(0xffffffffu, s3, 2);
        s4 += __shfl_xor_sync(0xffffffffu, s4, 2);
        s5 += __shfl_xor_sync(0xffffffffu, s5, 2);
        s6 += __shfl_xor_sync(0xffffffffu, s6, 2);

        const int sel = lane & 3;
        const int g   = wrp * 8 + (lane >> 2);           // 0..63
        const float vA4 = (sel == 0) ? s0 : (sel == 1) ? s1 : (sel == 2) ? s2 : s3;
        const float vB4 = (sel == 0) ? s4 : (sel == 1) ? s5 : s6;

        part[vi][sel][g] = vA4;
        if (sel < 3) part[vi][4 + sel][g] = vB4;
    }

    __syncthreads();

    // Phase A: reduce the 64 partials for each (vector, sum).
    if (t < 112) {
        const int v = t / 7;
        const int k = t % 7;
        const float* p = &part[v][k][0];
        float a = 0.0f;
#pragma unroll
        for (int j = 0; j < 64; ++j) a += p[(j + t) & 63];
        tot[v][k] = a;
    }
    __syncthreads();

    // Phase B: 6 outputs per vector, one thread each.
    if (t < 128) {
        const int v = t >> 3;
        const int j = t & 7;
        if (j < 6) {
            const int gv = v0 + v;
            const int n  = gv & 3;
            const int bt = gv >> 2;
            const float scale = rsqrtf(tot[v][0] * (1.0f / DIM) + EPS);
            if (j == 0) {
                out[gv] = fmaf(alpha_pre[0], tanhf(tot[v][1] * scale), b_pre[n]);
            } else if (j == 1) {
                out[NVEC + gv] = fmaf(alpha_post[0], tanhf(tot[v][2] * scale), b_post[n]);
            } else {
                const int i = j - 2;
                out[2 * NVEC + bt * 16 + i * 4 + n] =
                    fmaf(alpha_res[0], tanhf(tot[v][3 + i] * scale), b_res[4 * i + n]);
            }
        }
    }
}

extern "C" void kernel_launch(void* const* d_in, const int* in_sizes, int n_in,
                              void* d_out, int out_size)
{
    const float* x      = (const float*)d_in[0];   // [2,4096,4,2048]
    const float* rmsw   = (const float*)d_in[1];   // [2048]
    const float* apre   = (const float*)d_in[2];
    const float* apost  = (const float*)d_in[3];
    const float* ares   = (const float*)d_in[4];
    const float* tpre   = (const float*)d_in[5];   // [2048]
    const float* tpost  = (const float*)d_in[6];   // [2048]
    const float* tres   = (const float*)d_in[7];   // [4,2048]
    const float* bpre   = (const float*)d_in[8];
    const float* bpost  = (const float*)d_in[9];
    const float* bres   = (const float*)d_in[10];  // [4,4]
    float* out = (float*)d_out;

    cudaFuncSetAttribute(hcmaps_kernel,
                         cudaFuncAttributeMaxDynamicSharedMemorySize,
                         DSMEM_BYTES);

    hcmaps_kernel<<<NBLK, 256, DSMEM_BYTES>>>(x, rmsw, apre, apost, ares,
                                              tpre, tpost, tres,
                                              bpre, bpost, bres, out);
}